// round 1
// baseline (speedup 1.0000x reference)
#include <cuda_runtime.h>
#include <math.h>

#define N_ELEMS 131072

__device__ __forceinline__ float2 cmul(float2 a, float2 b) {
    return make_float2(a.x * b.x - a.y * b.y, a.x * b.y + a.y * b.x);
}

// Computes S = Re(U0^dagger (Z (x) I) U0) for the pair-0 2-qubit circuit.
// k index: bit1 = wire 2p (A, MSB), bit0 = wire 2p+1 (B, LSB).
__device__ void compute_S(const float* __restrict__ params, float* __restrict__ S) {
    // U[row][col], init identity
    float2 U[4][4];
#pragma unroll
    for (int r = 0; r < 4; r++)
#pragma unroll
        for (int c = 0; c < 4; c++)
            U[r][c] = make_float2(r == c ? 1.0f : 0.0f, 0.0f);

#pragma unroll
    for (int layer = 0; layer < 3; layer++) {
        const float* pp = params + layer * 16;  // pair 0 of this layer
        float t0 = pp[0], t1 = pp[1], t2 = pp[2], t3 = pp[3];

        // --- RZ(t0) on qubit A (bit 1 of row index): row *= e^{-i t0/2} if bit=0 else conj ---
        {
            float ch, sh;
            sincosf(0.5f * t0, &sh, &ch);
            float2 e0 = make_float2(ch, -sh);   // e^{-i t/2}
            float2 e1 = make_float2(ch, sh);    // e^{+i t/2}
#pragma unroll
            for (int r = 0; r < 4; r++) {
                float2 ph = ((r >> 1) & 1) ? e1 : e0;
#pragma unroll
                for (int c = 0; c < 4; c++) U[r][c] = cmul(ph, U[r][c]);
            }
        }
        // --- RX(t1) on qubit B (bit 0): mixes row pairs (0,1) and (2,3) ---
        {
            float ch, sh;
            sincosf(0.5f * t1, &sh, &ch);
            // new0 = c*r0 + (-i s)*r1 ; new1 = (-i s)*r0 + c*r1
#pragma unroll
            for (int base = 0; base < 4; base += 2) {
#pragma unroll
                for (int c = 0; c < 4; c++) {
                    float2 a = U[base][c], b = U[base + 1][c];
                    // (-i s) * v = (s*v.y, -s*v.x)
                    float2 misb = make_float2(sh * b.y, -sh * b.x);
                    float2 misa = make_float2(sh * a.y, -sh * a.x);
                    U[base][c]     = make_float2(ch * a.x + misb.x, ch * a.y + misb.y);
                    U[base + 1][c] = make_float2(misa.x + ch * b.x, misa.y + ch * b.y);
                }
            }
        }
        // --- CNOT(A -> B): swap rows 2 and 3 ---
        {
#pragma unroll
            for (int c = 0; c < 4; c++) {
                float2 tmp = U[2][c];
                U[2][c] = U[3][c];
                U[3][c] = tmp;
            }
        }
        // --- RZ(t2) on qubit B (bit 0) ---
        {
            float ch, sh;
            sincosf(0.5f * t2, &sh, &ch);
            float2 e0 = make_float2(ch, -sh);
            float2 e1 = make_float2(ch, sh);
#pragma unroll
            for (int r = 0; r < 4; r++) {
                float2 ph = (r & 1) ? e1 : e0;
#pragma unroll
                for (int c = 0; c < 4; c++) U[r][c] = cmul(ph, U[r][c]);
            }
        }
        // --- RX(t3) on qubit B (bit 0) ---
        {
            float ch, sh;
            sincosf(0.5f * t3, &sh, &ch);
#pragma unroll
            for (int base = 0; base < 4; base += 2) {
#pragma unroll
                for (int c = 0; c < 4; c++) {
                    float2 a = U[base][c], b = U[base + 1][c];
                    float2 misb = make_float2(sh * b.y, -sh * b.x);
                    float2 misa = make_float2(sh * a.y, -sh * a.x);
                    U[base][c]     = make_float2(ch * a.x + misb.x, ch * a.y + misb.y);
                    U[base + 1][c] = make_float2(misa.x + ch * b.x, misa.y + ch * b.y);
                }
            }
        }
    }

    // S[k][l] = Re( sum_m conj(U[m][k]) * z_m * U[m][l] ), z = (+1,+1,-1,-1)
#pragma unroll
    for (int k = 0; k < 4; k++) {
#pragma unroll
        for (int l = 0; l < 4; l++) {
            float acc = 0.0f;
#pragma unroll
            for (int m = 0; m < 4; m++) {
                float zs = (m < 2) ? 1.0f : -1.0f;
                acc += zs * (U[m][k].x * U[m][l].x + U[m][k].y * U[m][l].y);
            }
            S[k * 4 + l] = acc;
        }
    }
}

__global__ void __launch_bounds__(256) qcnn_kernel(
    const float* __restrict__ inputs,   // (B, 8) row-major
    const float* __restrict__ params,   // (48,)
    float* __restrict__ out,            // (B,)
    int n)
{
    __shared__ float sS[16];
    if (threadIdx.x == 0) {
        compute_S(params, sS);
    }
    __syncthreads();

    int b = blockIdx.x * blockDim.x + threadIdx.x;
    if (b >= n) return;

    // only x[b,0] and x[b,1] matter (Z_0 observable; circuit factorizes over pairs)
    float2 x01 = reinterpret_cast<const float2*>(inputs)[b * 4];

    float c0, s0, c1, s1;
    sincosf(0.5f * x01.x, &s0, &c0);
    sincosf(0.5f * x01.y, &s1, &c1);

    float psi0 = c0 * c1;
    float psi1 = c0 * s1;
    float psi2 = s0 * c1;
    float psi3 = s0 * s1;
    float psi[4] = {psi0, psi1, psi2, psi3};

    float z = 0.0f;
#pragma unroll
    for (int k = 0; k < 4; k++) {
        float rowacc = 0.0f;
#pragma unroll
        for (int l = 0; l < 4; l++) rowacc = fmaf(sS[k * 4 + l], psi[l], rowacc);
        z = fmaf(psi[k], rowacc, z);
    }

    out[b] = 1.0f / (1.0f + expf(-z));
}

extern "C" void kernel_launch(void* const* d_in, const int* in_sizes, int n_in,
                              void* d_out, int out_size) {
    const float* inputs = (const float*)d_in[0];
    const float* params = (const float*)d_in[1];
    float* out = (float*)d_out;

    int n = out_size;  // 131072 elements
    int threads = 256;
    int blocks = (n + threads - 1) / threads;
    qcnn_kernel<<<blocks, threads>>>(inputs, params, out, n);
}

// round 2
// speedup vs baseline: 1.3913x; 1.3913x over previous
#include <cuda_runtime.h>
#include <math.h>

__device__ __forceinline__ float2 cmul(float2 a, float2 b) {
    return make_float2(a.x * b.x - a.y * b.y, a.x * b.y + a.y * b.x);
}

// Computes M (3x3) such that z = (1, cosx0, sinx0) . M . (1, cosx1, sinx1)^T
// where z = psi^T S psi, S = Re(U^dag (Z(x)I) U) for the pair-0 circuit.
__device__ void compute_M(const float* __restrict__ params, float* __restrict__ M) {
    float2 U[4][4];
#pragma unroll
    for (int r = 0; r < 4; r++)
#pragma unroll
        for (int c = 0; c < 4; c++)
            U[r][c] = make_float2(r == c ? 1.0f : 0.0f, 0.0f);

#pragma unroll
    for (int layer = 0; layer < 3; layer++) {
        const float* pp = params + layer * 16;  // pair 0 of this layer
        float t0 = pp[0], t1 = pp[1], t2 = pp[2], t3 = pp[3];

        // RZ(t0) on qubit A (row bit 1)
        {
            float ch, sh;
            __sincosf(0.5f * t0, &sh, &ch);
            float2 e0 = make_float2(ch, -sh);
            float2 e1 = make_float2(ch, sh);
#pragma unroll
            for (int r = 0; r < 4; r++) {
                float2 ph = ((r >> 1) & 1) ? e1 : e0;
#pragma unroll
                for (int c = 0; c < 4; c++) U[r][c] = cmul(ph, U[r][c]);
            }
        }
        // RX(t1) on qubit B (row bit 0)
        {
            float ch, sh;
            __sincosf(0.5f * t1, &sh, &ch);
#pragma unroll
            for (int base = 0; base < 4; base += 2) {
#pragma unroll
                for (int c = 0; c < 4; c++) {
                    float2 a = U[base][c], b = U[base + 1][c];
                    float2 misb = make_float2(sh * b.y, -sh * b.x);
                    float2 misa = make_float2(sh * a.y, -sh * a.x);
                    U[base][c]     = make_float2(ch * a.x + misb.x, ch * a.y + misb.y);
                    U[base + 1][c] = make_float2(misa.x + ch * b.x, misa.y + ch * b.y);
                }
            }
        }
        // CNOT(A->B): swap rows 2 and 3
        {
#pragma unroll
            for (int c = 0; c < 4; c++) {
                float2 tmp = U[2][c]; U[2][c] = U[3][c]; U[3][c] = tmp;
            }
        }
        // RZ(t2) on qubit B
        {
            float ch, sh;
            __sincosf(0.5f * t2, &sh, &ch);
            float2 e0 = make_float2(ch, -sh);
            float2 e1 = make_float2(ch, sh);
#pragma unroll
            for (int r = 0; r < 4; r++) {
                float2 ph = (r & 1) ? e1 : e0;
#pragma unroll
                for (int c = 0; c < 4; c++) U[r][c] = cmul(ph, U[r][c]);
            }
        }
        // RX(t3) on qubit B
        {
            float ch, sh;
            __sincosf(0.5f * t3, &sh, &ch);
#pragma unroll
            for (int base = 0; base < 4; base += 2) {
#pragma unroll
                for (int c = 0; c < 4; c++) {
                    float2 a = U[base][c], b = U[base + 1][c];
                    float2 misb = make_float2(sh * b.y, -sh * b.x);
                    float2 misa = make_float2(sh * a.y, -sh * a.x);
                    U[base][c]     = make_float2(ch * a.x + misb.x, ch * a.y + misb.y);
                    U[base + 1][c] = make_float2(misa.x + ch * b.x, misa.y + ch * b.y);
                }
            }
        }
    }

    // S[k][l] = Re( sum_m conj(U[m][k]) z_m U[m][l] ), z=(+1,+1,-1,-1), k=2a+b
    float S[4][4];
#pragma unroll
    for (int k = 0; k < 4; k++)
#pragma unroll
        for (int l = 0; l < 4; l++) {
            float acc = 0.0f;
#pragma unroll
            for (int m = 0; m < 4; m++) {
                float zs = (m < 2) ? 1.0f : -1.0f;
                acc += zs * (U[m][k].x * U[m][l].x + U[m][k].y * U[m][l].y);
            }
            S[k][l] = acc;
        }

    // Half-angle -> full-angle basis change:
    // A(x)[0][0]=(1+C)/2, A[0][1]=A[1][0]=S/2, A[1][1]=(1-C)/2
    // E[a][c][u]: coeffs of A[a][c] over basis (1, C, S)
    const float E[2][2][3] = {
        { {0.5f, 0.5f, 0.0f}, {0.0f, 0.0f, 0.5f} },
        { {0.0f, 0.0f, 0.5f}, {0.5f, -0.5f, 0.0f} }
    };

#pragma unroll
    for (int u = 0; u < 3; u++)
#pragma unroll
        for (int v = 0; v < 3; v++) {
            float acc = 0.0f;
#pragma unroll
            for (int a = 0; a < 2; a++)
#pragma unroll
                for (int c = 0; c < 2; c++)
#pragma unroll
                    for (int b = 0; b < 2; b++)
#pragma unroll
                        for (int d = 0; d < 2; d++)
                            acc += S[2 * a + b][2 * c + d] * E[a][c][u] * E[b][d][v];
            M[u * 3 + v] = acc;
        }
}

__global__ void __launch_bounds__(128, 8) qcnn_kernel(
    const float* __restrict__ inputs,   // (B, 8) row-major
    const float* __restrict__ params,   // (48,)
    float* __restrict__ out,            // (B,)
    int n)
{
    __shared__ float sM[9];
    if (threadIdx.x == 0) {
        compute_M(params, sM);
    }
    __syncthreads();

    int b = blockIdx.x * blockDim.x + threadIdx.x;
    if (b >= n) return;

    // only x[b,0] and x[b,1] matter (Z_0 observable; circuit factorizes over pairs)
    float2 x01 = __ldg(reinterpret_cast<const float2*>(inputs) + b * 4);

    float C0, S0, C1, S1;
    __sincosf(x01.x, &S0, &C0);
    __sincosf(x01.y, &S1, &C1);

    float m0 = sM[0], m1 = sM[1], m2 = sM[2];
    float m3 = sM[3], m4 = sM[4], m5 = sM[5];
    float m6 = sM[6], m7 = sM[7], m8 = sM[8];

    float t0 = fmaf(m2, S1, fmaf(m1, C1, m0));
    float t1 = fmaf(m5, S1, fmaf(m4, C1, m3));
    float t2 = fmaf(m8, S1, fmaf(m7, C1, m6));
    float z  = fmaf(t2, S0, fmaf(t1, C0, t0));

    out[b] = __fdividef(1.0f, 1.0f + __expf(-z));
}

extern "C" void kernel_launch(void* const* d_in, const int* in_sizes, int n_in,
                              void* d_out, int out_size) {
    const float* inputs = (const float*)d_in[0];
    const float* params = (const float*)d_in[1];
    float* out = (float*)d_out;

    int n = out_size;  // 131072
    int threads = 128;
    int blocks = (n + threads - 1) / threads;  // 1024
    qcnn_kernel<<<blocks, threads>>>(inputs, params, out, n);
}